// round 4
// baseline (speedup 1.0000x reference)
#include <cuda_runtime.h>

// ---------------- problem constants ----------------
#define T_LEN   16384
#define CH      128
#define BATCH   8
#define NLAYER  63
#define N0SKIP  27
#define KC      32

// layer kernel tiling
#define TM_L       128
#define AS_STRIDE  132
#define YS_STRIDE  132

// post kernel tiling
#define TM_P        64
#define AS2_STRIDE  68
#define S1_STRIDE   68
#define S2_STRIDE   133

#define ACT_ELEMS (8u * 16384u * 128u)   // 16,777,216

// smem sizes (floats)
#define SMEM_LAYER_FLOATS (KC*AS_STRIDE + KC*CH + CH*YS_STRIDE)                    // 25216
#define SMEM_POST_FLOATS  (KC*AS2_STRIDE + KC*CH + CH*S1_STRIDE + TM_P*S2_STRIDE)  // 23488
#define SMEM_LAYER_BYTES  (SMEM_LAYER_FLOATS * 4)   // 100864
#define SMEM_POST_BYTES   (SMEM_POST_FLOATS  * 4)   // 93952

// ---------------- device scratch (static; no runtime alloc) ----------------
__device__ float g_bufA[ACT_ELEMS];
__device__ float g_bufB[ACT_ELEMS];
__device__ float g_skip[ACT_ELEMS];
__device__ float g_w3t[NLAYER * 3 * CH * CH];   // [cnt][tap][i][o]
__device__ float g_wdt[NLAYER * CH * CH];       // [cnt][c][o]
__device__ float g_wst[NLAYER * CH * CH];       // [cnt][o][s]
__device__ float g_p1t[CH * CH];                // [c][n]
__device__ float g_p2t[CH * 256];               // [n][q]

// ---------------- packed f32x2 helpers ----------------
__device__ __forceinline__ unsigned long long fma2(unsigned long long a,
                                                   unsigned long long b,
                                                   unsigned long long c) {
    unsigned long long d;
    asm("fma.rn.f32x2 %0, %1, %2, %3;" : "=l"(d) : "l"(a), "l"(b), "l"(c));
    return d;
}
__device__ __forceinline__ unsigned long long dup2(float x) {
    unsigned long long d;
    asm("mov.b64 %0, {%1, %1};" : "=l"(d) : "f"(x));
    return d;
}
__device__ __forceinline__ unsigned long long pack2(float lo, float hi) {
    unsigned long long d;
    asm("mov.b64 %0, {%1, %2};" : "=l"(d) : "f"(lo), "f"(hi));
    return d;
}
__device__ __forceinline__ void unpack2(unsigned long long v, float& lo, float& hi) {
    asm("mov.b64 {%0, %1}, %2;" : "=f"(lo), "=f"(hi) : "l"(v));
}

// ---------------- weight pre-transpose ----------------
__global__ void prep_kernel(const float* __restrict__ dcnn_w,
                            const float* __restrict__ dense_w,
                            const float* __restrict__ skip_w,
                            const float* __restrict__ p1w,
                            const float* __restrict__ p2w) {
    int gs  = gridDim.x * blockDim.x;
    int tid = blockIdx.x * blockDim.x + threadIdx.x;

    const int N3 = NLAYER * 3 * CH * CH;
    for (int idx = tid; idx < N3; idx += gs) {
        int o   = idx & 127;
        int i   = (idx >> 7) & 127;
        int tap = (idx >> 14) % 3;
        int cnt = idx / (3 * CH * CH);
        g_w3t[idx] = dcnn_w[((cnt * CH + o) * CH + i) * 3 + tap];
    }
    const int N1 = NLAYER * CH * CH;
    for (int idx = tid; idx < N1; idx += gs) {
        int a    = idx & 127;         // inner dim of destination (output col)
        int bmid = (idx >> 7) & 127;  // middle dim of destination (k row)
        int cnt  = idx >> 14;
        // both are plain per-layer transposes of the last two dims
        g_wdt[idx] = dense_w[(cnt * CH + a) * CH + bmid];
        g_wst[idx] = skip_w[(cnt * CH + a) * CH + bmid];
    }
    for (int idx = tid; idx < CH * CH; idx += gs) {
        int n = idx & 127;
        int c = idx >> 7;
        g_p1t[idx] = p1w[n * CH + c];
    }
    for (int idx = tid; idx < CH * 256; idx += gs) {
        int q = idx & 255;
        int n = idx >> 8;
        g_p2t[idx] = p2w[q * CH + n];
    }
}

// ---------------- causal conv (k=25, pad 12), 1 -> 128 channels ----------------
__global__ void causal_kernel(const float* __restrict__ x,
                              const float* __restrict__ cw,
                              const float* __restrict__ cb) {
    __shared__ float xs[64 + 24];
    int b  = blockIdx.y;
    int t0 = blockIdx.x * 64;
    int c  = threadIdx.x;  // 0..127

    for (int i = threadIdx.x; i < 88; i += 128) {
        int t = t0 - 12 + i;
        xs[i] = ((unsigned)t < T_LEN) ? x[(size_t)b * T_LEN + t] : 0.f;
    }
    __syncthreads();

    float w[25];
#pragma unroll
    for (int k = 0; k < 25; ++k) w[k] = cw[c * 25 + k];
    float bias = cb[c];

    float* out = g_bufA + (size_t)b * T_LEN * CH;
    for (int tt = 0; tt < 64; ++tt) {
        float s = bias;
#pragma unroll
        for (int k = 0; k < 25; ++k) s += w[k] * xs[tt + k];
        out[(size_t)(t0 + tt) * CH + c] = s;
    }
}

// ---------------- one residual layer ----------------
// y = relu(dconv(relu(xin)) + b3) ; skip (+)= y@Ws + bs ; xout = y@Wd + bd + xin
__global__ void __launch_bounds__(256, 2)
layer_kernel(int cnt, int dil, int skip_mode, int do_dense, int pp,
             const float* __restrict__ dcnn_b,
             const float* __restrict__ dense_b,
             const float* __restrict__ skip_b) {
    extern __shared__ float sm[];
    float* As  = sm;                       // [KC][AS_STRIDE]  transposed h tile
    float* Bs  = sm + KC * AS_STRIDE;      // [KC][CH]
    float* Yst = Bs + KC * CH;             // [CH][YS_STRIDE]  y transposed [o][m]

    const float* xin  = pp ? g_bufB : g_bufA;
    float*       xout = pp ? g_bufA : g_bufB;

    int b    = blockIdx.y;
    int t0   = blockIdx.x * TM_L;
    int tid  = threadIdx.x;
    int lane = tid & 31, warp = tid >> 5;
    int c4   = lane * 4;
    int r16  = warp * 16;

    const float* xinB = xin + (size_t)b * T_LEN * CH;

    unsigned long long acc[8][4];
#pragma unroll
    for (int i = 0; i < 8; ++i)
#pragma unroll
        for (int j = 0; j < 4; ++j) acc[i][j] = 0ULL;

    const float* w3base = g_w3t + (size_t)cnt * 3 * CH * CH;

    // ---- stage 1: y = relu(3-tap dilated conv of relu(xin)) ----
    for (int tap = 0; tap < 3; ++tap) {
        int shift = (tap - 1) * dil;
        const float* wt = w3base + tap * CH * CH;
        for (int k0 = 0; k0 < CH; k0 += KC) {
            __syncthreads();
            // A tile: As[kk][m] = relu(xin[t0+m+shift][k0+kk])
#pragma unroll
            for (int i = 0; i < 4; ++i) {
                int e4 = tid + i * 256;        // 0..1023 (float4 units)
                int m  = e4 >> 3;
                int kq = (e4 & 7) * 4;
                int t  = t0 + m + shift;
                float4 v = make_float4(0.f, 0.f, 0.f, 0.f);
                if ((unsigned)t < T_LEN)
                    v = *(const float4*)(xinB + (size_t)t * CH + (k0 + kq));
                As[(kq + 0) * AS_STRIDE + m] = fmaxf(v.x, 0.f);
                As[(kq + 1) * AS_STRIDE + m] = fmaxf(v.y, 0.f);
                As[(kq + 2) * AS_STRIDE + m] = fmaxf(v.z, 0.f);
                As[(kq + 3) * AS_STRIDE + m] = fmaxf(v.w, 0.f);
            }
            // B tile: contiguous copy of wt[k0..k0+31][*]
            {
                const float4* src = (const float4*)(wt + k0 * CH);
                float4* dst = (float4*)Bs;
#pragma unroll
                for (int i = 0; i < 4; ++i) dst[tid + i * 256] = src[tid + i * 256];
            }
            __syncthreads();
#pragma unroll
            for (int kk = 0; kk < KC; ++kk) {
                const float* ar = &As[kk * AS_STRIDE + r16];
                ulonglong2 A0 = *(const ulonglong2*)(ar + 0);
                ulonglong2 A1 = *(const ulonglong2*)(ar + 4);
                ulonglong2 A2 = *(const ulonglong2*)(ar + 8);
                ulonglong2 A3 = *(const ulonglong2*)(ar + 12);
                float4 bv = *(const float4*)&Bs[kk * CH + c4];
                unsigned long long b0 = dup2(bv.x), b1 = dup2(bv.y),
                                   b2 = dup2(bv.z), b3 = dup2(bv.w);
                unsigned long long ap[8] = {A0.x, A0.y, A1.x, A1.y,
                                            A2.x, A2.y, A3.x, A3.y};
#pragma unroll
                for (int rp = 0; rp < 8; ++rp) {
                    acc[rp][0] = fma2(ap[rp], b0, acc[rp][0]);
                    acc[rp][1] = fma2(ap[rp], b1, acc[rp][1]);
                    acc[rp][2] = fma2(ap[rp], b2, acc[rp][2]);
                    acc[rp][3] = fma2(ap[rp], b3, acc[rp][3]);
                }
            }
        }
    }
    // stage-1 epilogue: bias + relu -> Yst[o][m]
    {
        const float4 b3v = *(const float4*)&dcnn_b[cnt * CH + c4];
        float bj[4] = {b3v.x, b3v.y, b3v.z, b3v.w};
#pragma unroll
        for (int rp = 0; rp < 8; ++rp) {
            int m = r16 + 2 * rp;
#pragma unroll
            for (int j = 0; j < 4; ++j) {
                float lo, hi;
                unpack2(acc[rp][j], lo, hi);
                lo = fmaxf(lo + bj[j], 0.f);
                hi = fmaxf(hi + bj[j], 0.f);
                *(unsigned long long*)&Yst[(c4 + j) * YS_STRIDE + m] = pack2(lo, hi);
            }
        }
    }
    __syncthreads();

    // ---- stage 2: skip GEMM (g=0) and dense GEMM (g=1) ----
    for (int g = 0; g < 2; ++g) {
        if (g == 0 && skip_mode == 0) continue;
        if (g == 1 && !do_dense) continue;
        const float* W = (g == 0) ? (g_wst + (size_t)cnt * CH * CH)
                                  : (g_wdt + (size_t)cnt * CH * CH);
#pragma unroll
        for (int i = 0; i < 8; ++i)
#pragma unroll
            for (int j = 0; j < 4; ++j) acc[i][j] = 0ULL;

        for (int k0 = 0; k0 < CH; k0 += KC) {
            __syncthreads();
            {
                const float4* src = (const float4*)(W + k0 * CH);
                float4* dst = (float4*)Bs;
#pragma unroll
                for (int i = 0; i < 4; ++i) dst[tid + i * 256] = src[tid + i * 256];
            }
            __syncthreads();
#pragma unroll
            for (int kk = 0; kk < KC; ++kk) {
                const float* ar = &Yst[(k0 + kk) * YS_STRIDE + r16];
                ulonglong2 A0 = *(const ulonglong2*)(ar + 0);
                ulonglong2 A1 = *(const ulonglong2*)(ar + 4);
                ulonglong2 A2 = *(const ulonglong2*)(ar + 8);
                ulonglong2 A3 = *(const ulonglong2*)(ar + 12);
                float4 bv = *(const float4*)&Bs[kk * CH + c4];
                unsigned long long b0 = dup2(bv.x), b1 = dup2(bv.y),
                                   b2 = dup2(bv.z), b3 = dup2(bv.w);
                unsigned long long ap[8] = {A0.x, A0.y, A1.x, A1.y,
                                            A2.x, A2.y, A3.x, A3.y};
#pragma unroll
                for (int rp = 0; rp < 8; ++rp) {
                    acc[rp][0] = fma2(ap[rp], b0, acc[rp][0]);
                    acc[rp][1] = fma2(ap[rp], b1, acc[rp][1]);
                    acc[rp][2] = fma2(ap[rp], b2, acc[rp][2]);
                    acc[rp][3] = fma2(ap[rp], b3, acc[rp][3]);
                }
            }
        }
        if (g == 0) {
            const float4 bsv = *(const float4*)&skip_b[cnt * CH + c4];
            float bj[4] = {bsv.x, bsv.y, bsv.z, bsv.w};
            float* skB = g_skip + (size_t)b * T_LEN * CH;
#pragma unroll
            for (int rp = 0; rp < 8; ++rp) {
                int m = r16 + 2 * rp;
                size_t o0 = (size_t)(t0 + m) * CH + c4;
                size_t o1 = o0 + CH;
#pragma unroll
                for (int j = 0; j < 4; ++j) {
                    float lo, hi;
                    unpack2(acc[rp][j], lo, hi);
                    lo += bj[j];
                    hi += bj[j];
                    if (skip_mode == 2) { lo += skB[o0 + j]; hi += skB[o1 + j]; }
                    skB[o0 + j] = lo;
                    skB[o1 + j] = hi;
                }
            }
        } else {
            const float4 bdv = *(const float4*)&dense_b[cnt * CH + c4];
            float bj[4] = {bdv.x, bdv.y, bdv.z, bdv.w};
            float* xoB = xout + (size_t)b * T_LEN * CH;
#pragma unroll
            for (int rp = 0; rp < 8; ++rp) {
                int m = r16 + 2 * rp;
                size_t o0 = (size_t)(t0 + m) * CH + c4;
                size_t o1 = o0 + CH;
#pragma unroll
                for (int j = 0; j < 4; ++j) {
                    float lo, hi;
                    unpack2(acc[rp][j], lo, hi);
                    lo += bj[j] + xinB[o0 + j];
                    hi += bj[j] + xinB[o1 + j];
                    xoB[o0 + j] = lo;
                    xoB[o1 + j] = hi;
                }
            }
        }
    }
}

// ---------------- post head: out = W2 @ relu(W1 @ relu(skip) + b1) + b2 ----------------
__global__ void __launch_bounds__(256, 2)
post_kernel(const float* __restrict__ p1b, const float* __restrict__ p2b,
            float* __restrict__ out) {
    extern __shared__ float sm[];
    float* As  = sm;                             // [KC][AS2_STRIDE]
    float* Bs  = As + KC * AS2_STRIDE;           // [KC][CH]
    float* S1t = Bs + KC * CH;                   // [CH][S1_STRIDE]  (s1 transposed [n][m])
    float* S2  = S1t + CH * S1_STRIDE;           // [TM_P][S2_STRIDE]

    int b    = blockIdx.y;
    int t0   = blockIdx.x * TM_P;
    int tid  = threadIdx.x;
    int lane = tid & 31, warp = tid >> 5;
    int c4   = lane * 4;
    int r8   = warp * 8;

    const float* skB = g_skip + (size_t)b * T_LEN * CH;

    unsigned long long acc[4][4];
#pragma unroll
    for (int i = 0; i < 4; ++i)
#pragma unroll
        for (int j = 0; j < 4; ++j) acc[i][j] = 0ULL;

    // ---- stage A: s1 = relu(relu(skip) @ p1t + b1) ----
    for (int k0 = 0; k0 < CH; k0 += KC) {
        __syncthreads();
#pragma unroll
        for (int i = 0; i < 2; ++i) {
            int e4 = tid + i * 256;       // 0..511 (float4 units, 64x32)
            int m  = e4 >> 3;
            int kq = (e4 & 7) * 4;
            float4 v = *(const float4*)(skB + (size_t)(t0 + m) * CH + k0 + kq);
            As[(kq + 0) * AS2_STRIDE + m] = fmaxf(v.x, 0.f);
            As[(kq + 1) * AS2_STRIDE + m] = fmaxf(v.y, 0.f);
            As[(kq + 2) * AS2_STRIDE + m] = fmaxf(v.z, 0.f);
            As[(kq + 3) * AS2_STRIDE + m] = fmaxf(v.w, 0.f);
        }
        {
            const float4* src = (const float4*)(g_p1t + k0 * CH);
            float4* dst = (float4*)Bs;
#pragma unroll
            for (int i = 0; i < 4; ++i) dst[tid + i * 256] = src[tid + i * 256];
        }
        __syncthreads();
#pragma unroll
        for (int kk = 0; kk < KC; ++kk) {
            const float* ar = &As[kk * AS2_STRIDE + r8];
            ulonglong2 A0 = *(const ulonglong2*)(ar + 0);
            ulonglong2 A1 = *(const ulonglong2*)(ar + 4);
            float4 bv = *(const float4*)&Bs[kk * CH + c4];
            unsigned long long b0 = dup2(bv.x), b1 = dup2(bv.y),
                               b2 = dup2(bv.z), b3 = dup2(bv.w);
            unsigned long long ap[4] = {A0.x, A0.y, A1.x, A1.y};
#pragma unroll
            for (int rp = 0; rp < 4; ++rp) {
                acc[rp][0] = fma2(ap[rp], b0, acc[rp][0]);
                acc[rp][1] = fma2(ap[rp], b1, acc[rp][1]);
                acc[rp][2] = fma2(ap[rp], b2, acc[rp][2]);
                acc[rp][3] = fma2(ap[rp], b3, acc[rp][3]);
            }
        }
    }
    {
        const float4 b1v = *(const float4*)&p1b[c4];
        float bj[4] = {b1v.x, b1v.y, b1v.z, b1v.w};
#pragma unroll
        for (int rp = 0; rp < 4; ++rp) {
            int m = r8 + 2 * rp;
#pragma unroll
            for (int j = 0; j < 4; ++j) {
                float lo, hi;
                unpack2(acc[rp][j], lo, hi);
                lo = fmaxf(lo + bj[j], 0.f);
                hi = fmaxf(hi + bj[j], 0.f);
                *(unsigned long long*)&S1t[(c4 + j) * S1_STRIDE + m] = pack2(lo, hi);
            }
        }
    }
    __syncthreads();

    // ---- stage B: out = s1 @ p2t + b2, in two 128-wide halves ----
    for (int half = 0; half < 2; ++half) {
#pragma unroll
        for (int i = 0; i < 4; ++i)
#pragma unroll
            for (int j = 0; j < 4; ++j) acc[i][j] = 0ULL;

        for (int k0 = 0; k0 < CH; k0 += KC) {
            __syncthreads();
#pragma unroll
            for (int i = 0; i < 4; ++i) {
                int e  = tid + i * 256;        // 0..1023 (float4 units)
                int kk = e >> 5;
                int o4 = (e & 31) * 4;
                *(float4*)&Bs[kk * CH + o4] =
                    *(const float4*)(g_p2t + (size_t)(k0 + kk) * 256 + half * 128 + o4);
            }
            __syncthreads();
#pragma unroll
            for (int kk = 0; kk < KC; ++kk) {
                const float* ar = &S1t[(k0 + kk) * S1_STRIDE + r8];
                ulonglong2 A0 = *(const ulonglong2*)(ar + 0);
                ulonglong2 A1 = *(const ulonglong2*)(ar + 4);
                float4 bv = *(const float4*)&Bs[kk * CH + c4];
                unsigned long long b0 = dup2(bv.x), b1 = dup2(bv.y),
                                   b2 = dup2(bv.z), b3 = dup2(bv.w);
                unsigned long long ap[4] = {A0.x, A0.y, A1.x, A1.y};
#pragma unroll
                for (int rp = 0; rp < 4; ++rp) {
                    acc[rp][0] = fma2(ap[rp], b0, acc[rp][0]);
                    acc[rp][1] = fma2(ap[rp], b1, acc[rp][1]);
                    acc[rp][2] = fma2(ap[rp], b2, acc[rp][2]);
                    acc[rp][3] = fma2(ap[rp], b3, acc[rp][3]);
                }
            }
        }
        // epilogue to S2 (t-major padded), then coalesced transpose-store
        {
            const float4 b2v = *(const float4*)&p2b[half * 128 + c4];
            float bj[4] = {b2v.x, b2v.y, b2v.z, b2v.w};
#pragma unroll
            for (int rp = 0; rp < 4; ++rp) {
                int m = r8 + 2 * rp;
#pragma unroll
                for (int j = 0; j < 4; ++j) {
                    float lo, hi;
                    unpack2(acc[rp][j], lo, hi);
                    S2[m * S2_STRIDE + c4 + j]       = lo + bj[j];
                    S2[(m + 1) * S2_STRIDE + c4 + j] = hi + bj[j];
                }
            }
        }
        __syncthreads();
        float* outB = out + ((size_t)b * 256 + half * 128) * T_LEN;
#pragma unroll
        for (int i = 0; i < 32; ++i) {
            int e = tid + i * 256;   // 8192 = 128 q x 64 t
            int q = e >> 6;
            int t = e & 63;
            outB[(size_t)q * T_LEN + t0 + t] = S2[t * S2_STRIDE + q];
        }
        __syncthreads();
    }
}

// ---------------- launch ----------------
extern "C" void kernel_launch(void* const* d_in, const int* in_sizes, int n_in,
                              void* d_out, int out_size) {
    (void)in_sizes; (void)n_in; (void)out_size;
    const float* x        = (const float*)d_in[0];
    const float* causal_w = (const float*)d_in[1];
    const float* causal_b = (const float*)d_in[2];
    const float* dcnn_w   = (const float*)d_in[3];
    const float* dcnn_b   = (const float*)d_in[4];
    const float* dense_w  = (const float*)d_in[5];
    const float* dense_b  = (const float*)d_in[6];
    const float* skip_w   = (const float*)d_in[7];
    const float* skip_b   = (const float*)d_in[8];
    const float* p1w      = (const float*)d_in[9];
    const float* p1b      = (const float*)d_in[10];
    const float* p2w      = (const float*)d_in[11];
    const float* p2b      = (const float*)d_in[12];
    float* out = (float*)d_out;

    cudaFuncSetAttribute(layer_kernel, cudaFuncAttributeMaxDynamicSharedMemorySize,
                         SMEM_LAYER_BYTES);
    cudaFuncSetAttribute(post_kernel, cudaFuncAttributeMaxDynamicSharedMemorySize,
                         SMEM_POST_BYTES);

    prep_kernel<<<512, 256>>>(dcnn_w, dense_w, skip_w, p1w, p2w);
    causal_kernel<<<dim3(T_LEN / 64, BATCH), 128>>>(x, causal_w, causal_b);

    for (int cnt = 0; cnt < NLAYER; ++cnt) {
        int dil       = 1 << (cnt % 9);
        int skip_mode = (cnt < N0SKIP) ? 0 : ((cnt == N0SKIP) ? 1 : 2);
        int do_dense  = (cnt != NLAYER - 1);
        int pp        = cnt & 1;
        layer_kernel<<<dim3(T_LEN / TM_L, BATCH), 256, SMEM_LAYER_BYTES>>>(
            cnt, dil, skip_mode, do_dense, pp, dcnn_b, dense_b, skip_b);
    }

    post_kernel<<<dim3(T_LEN / TM_P, BATCH), 256, SMEM_POST_BYTES>>>(p1b, p2b, out);
}